// round 1
// baseline (speedup 1.0000x reference)
#include <cuda_runtime.h>
#include <math.h>

#define BATCH 4
#define SEQ   2048
#define CDIM  2048
#define HDIM  128
#define ROWS  (BATCH*SEQ)

// Scratch for Q,K,V projections (allocation-free device globals): 3 x 4 MB
__device__ float g_q[ROWS*HDIM];
__device__ float g_k[ROWS*HDIM];
__device__ float g_v[ROWS*HDIM];

// ---------------------------------------------------------------------------
// Kernel 1: fused QKV projection  (x[8192,2048] @ w[2048,128] + b) x3
// Tile: 32 rows x 128 cols, K-tile = 16. 256 threads: ty=row (32), tx=colgrp (8)
// Each thread owns cols {tx*4 + 32*j + 0..3 : j=0..3} of its row, for q,k,v.
// ---------------------------------------------------------------------------
#define BM 32
#define KT 16

__global__ __launch_bounds__(256) void qkv_kernel(
    const float* __restrict__ x,
    const float* __restrict__ wq, const float* __restrict__ bq,
    const float* __restrict__ wk, const float* __restrict__ bk,
    const float* __restrict__ wv, const float* __restrict__ bv)
{
    __shared__ float xs[BM][KT];          // 2 KB
    __shared__ float ws[3][KT][HDIM];     // 24 KB

    const int tid = threadIdx.x;
    const int ty  = tid >> 3;             // 0..31 (row within tile)
    const int tx  = tid & 7;              // 0..7  (column group)
    const int row = blockIdx.x * BM + ty;

    float acc[3][16];
    #pragma unroll
    for (int m = 0; m < 3; m++)
        #pragma unroll
        for (int i = 0; i < 16; i++) acc[m][i] = 0.f;

    for (int k0 = 0; k0 < CDIM; k0 += KT) {
        // load x tile: 32x16 = 512 floats, 2 per thread
        #pragma unroll
        for (int rep = 0; rep < 2; rep++) {
            int i = tid + rep * 256;
            int r = i >> 4, c = i & 15;
            xs[r][c] = x[(size_t)(blockIdx.x * BM + r) * CDIM + k0 + c];
        }
        // load w tiles: 3 x 16 x 128 floats = 1536 float4, 6 per thread
        #pragma unroll
        for (int rep = 0; rep < 6; rep++) {
            int i   = tid + rep * 256;     // 0..1535
            int m   = i >> 9;              // /512 float4 per matrix
            int rem = i & 511;
            int kk  = rem >> 5;            // 0..15
            int cc  = rem & 31;            // 0..31 (float4 col)
            const float* w = (m == 0) ? wq : ((m == 1) ? wk : wv);
            reinterpret_cast<float4*>(&ws[m][kk][0])[cc] =
                reinterpret_cast<const float4*>(w + (size_t)(k0 + kk) * HDIM)[cc];
        }
        __syncthreads();

        #pragma unroll
        for (int kk = 0; kk < KT; kk++) {
            float xv = xs[ty][kk];
            #pragma unroll
            for (int m = 0; m < 3; m++) {
                #pragma unroll
                for (int j = 0; j < 4; j++) {
                    // 8 distinct float4 addrs across tx -> conflict-free broadcast
                    float4 w4 = *reinterpret_cast<const float4*>(&ws[m][kk][tx * 4 + 32 * j]);
                    acc[m][j*4+0] = fmaf(xv, w4.x, acc[m][j*4+0]);
                    acc[m][j*4+1] = fmaf(xv, w4.y, acc[m][j*4+1]);
                    acc[m][j*4+2] = fmaf(xv, w4.z, acc[m][j*4+2]);
                    acc[m][j*4+3] = fmaf(xv, w4.w, acc[m][j*4+3]);
                }
            }
        }
        __syncthreads();
    }

    // bias + writeout
    float*       outp[3] = { g_q, g_k, g_v };
    const float* bp[3]   = { bq,  bk,  bv  };
    #pragma unroll
    for (int m = 0; m < 3; m++) {
        #pragma unroll
        for (int j = 0; j < 4; j++) {
            int col = tx * 4 + 32 * j;
            float4 b4 = *reinterpret_cast<const float4*>(bp[m] + col);
            float4 r;
            r.x = acc[m][j*4+0] + b4.x;
            r.y = acc[m][j*4+1] + b4.y;
            r.z = acc[m][j*4+2] + b4.z;
            r.w = acc[m][j*4+3] + b4.w;
            *reinterpret_cast<float4*>(outp[m] + (size_t)row * HDIM + col) = r;
        }
    }
}

// ---------------------------------------------------------------------------
// Kernel 2: causal flash attention, fp32, online softmax.
// 1 warp per query, 8 queries (warps) per block, 32-key K/V tiles in shared.
// Score phase: lane j owns key j, lane-rotated float4 reads (conflict-free).
// Output phase: lane owns dims [lane*4 .. lane*4+3].
// ---------------------------------------------------------------------------
#define TQ   8
#define TKEY 32

__global__ __launch_bounds__(256) void attn_kernel(float* __restrict__ out)
{
    __shared__ float ks[TKEY][HDIM];   // 16 KB
    __shared__ float vs[TKEY][HDIM];   // 16 KB
    __shared__ float qs[TQ][HDIM];     // 4 KB

    const int tid  = threadIdx.x;
    const int lane = tid & 31;
    const int w    = tid >> 5;                 // warp index = query within block
    const int b    = blockIdx.y;
    const int q0   = blockIdx.x * TQ;
    const int t    = q0 + w;                   // this warp's query position
    const int rowbase = b * SEQ;

    const float scale = rsqrtf((float)CDIM);   // NOTE: 1/sqrt(n_embd), per reference

    // load q tile (pre-scaled): 8x128 floats = 256 float4, 1 per thread
    {
        int r = tid >> 5, c = tid & 31;
        float4 q4 = reinterpret_cast<const float4*>(
            g_q + (size_t)(rowbase + q0 + r) * HDIM)[c];
        q4.x *= scale; q4.y *= scale; q4.z *= scale; q4.w *= scale;
        reinterpret_cast<float4*>(&qs[r][0])[c] = q4;
    }
    __syncthreads();

    float  m = -INFINITY, l = 0.f;
    float4 o = make_float4(0.f, 0.f, 0.f, 0.f);

    const int tmax   = q0 + TQ - 1;
    const int ntiles = tmax / TKEY + 1;

    for (int kt = 0; kt < ntiles; kt++) {
        // cooperative K/V tile load: 2 x 1024 float4, 4 each per thread
        const float* kg = g_k + (size_t)(rowbase + kt * TKEY) * HDIM;
        const float* vg = g_v + (size_t)(rowbase + kt * TKEY) * HDIM;
        #pragma unroll
        for (int rep = 0; rep < 4; rep++) {
            int i = tid + rep * 256;           // 0..1023
            int r = i >> 5, c = i & 31;
            reinterpret_cast<float4*>(&ks[r][0])[c] =
                reinterpret_cast<const float4*>(kg + (size_t)r * HDIM)[c];
            reinterpret_cast<float4*>(&vs[r][0])[c] =
                reinterpret_cast<const float4*>(vg + (size_t)r * HDIM)[c];
        }
        __syncthreads();

        // score: lane j computes q . k_j  (lane-rotated for bank-conflict-free)
        float s = 0.f;
        #pragma unroll
        for (int dd = 0; dd < 32; dd++) {
            int c = (dd + lane) & 31;
            float4 k4 = reinterpret_cast<const float4*>(&ks[lane][0])[c];
            float4 q4 = reinterpret_cast<const float4*>(&qs[w][0])[c];
            s = fmaf(k4.x, q4.x, s);
            s = fmaf(k4.y, q4.y, s);
            s = fmaf(k4.z, q4.z, s);
            s = fmaf(k4.w, q4.w, s);
        }
        int key = kt * TKEY + lane;
        if (key > t) s = -INFINITY;            // causal mask

        // online softmax update (warp-wide)
        float mt = s;
        #pragma unroll
        for (int off = 16; off; off >>= 1)
            mt = fmaxf(mt, __shfl_xor_sync(0xffffffffu, mt, off));
        float mnew = fmaxf(m, mt);             // finite: tile always has >=1 valid key
        float p    = __expf(s - mnew);         // masked lanes -> exp(-inf) = 0
        float corr = __expf(m - mnew);         // first tile: exp(-inf) = 0

        float psum = p;
        #pragma unroll
        for (int off = 16; off; off >>= 1)
            psum += __shfl_xor_sync(0xffffffffu, psum, off);

        l   = l * corr + psum;
        o.x *= corr; o.y *= corr; o.z *= corr; o.w *= corr;

        #pragma unroll
        for (int j = 0; j < TKEY; j++) {
            float  pj = __shfl_sync(0xffffffffu, p, j);
            float4 v4 = reinterpret_cast<const float4*>(&vs[j][0])[lane];
            o.x = fmaf(pj, v4.x, o.x);
            o.y = fmaf(pj, v4.y, o.y);
            o.z = fmaf(pj, v4.z, o.z);
            o.w = fmaf(pj, v4.w, o.w);
        }
        m = mnew;
        __syncthreads();
    }

    float inv = 1.f / l;
    o.x *= inv; o.y *= inv; o.z *= inv; o.w *= inv;
    reinterpret_cast<float4*>(out + (size_t)(rowbase + t) * HDIM)[lane] = o;
}

// ---------------------------------------------------------------------------
extern "C" void kernel_launch(void* const* d_in, const int* in_sizes, int n_in,
                              void* d_out, int out_size)
{
    const float* x  = (const float*)d_in[0];
    const float* wq = (const float*)d_in[1];
    const float* bq = (const float*)d_in[2];
    const float* wk = (const float*)d_in[3];
    const float* bk = (const float*)d_in[4];
    const float* wv = (const float*)d_in[5];
    const float* bv = (const float*)d_in[6];
    float* out = (float*)d_out;

    qkv_kernel<<<ROWS / BM, 256>>>(x, wq, bq, wk, bk, wv, bv);
    attn_kernel<<<dim3(SEQ / TQ, BATCH), 256>>>(out);
}

// round 3
// speedup vs baseline: 5.4101x; 5.4101x over previous
#include <cuda_runtime.h>
#include <cuda_bf16.h>
#include <cuda_fp16.h>
#include <cstdint>
#include <math.h>

#define BATCH 4
#define SEQ   2048
#define CDIM  2048
#define HDIM  128
#define ROWS  (BATCH*SEQ)

// ---------------------------------------------------------------------------
// Device scratch (allocation-free)
// ---------------------------------------------------------------------------
__device__ __align__(16) __nv_bfloat16 g_xhi[(size_t)ROWS*CDIM];     // 32 MB
__device__ __align__(16) __nv_bfloat16 g_xlo[(size_t)ROWS*CDIM];     // 32 MB
__device__ __align__(16) __nv_bfloat16 g_wthi[3*(size_t)HDIM*CDIM];  // W^T hi
__device__ __align__(16) __nv_bfloat16 g_wtlo[3*(size_t)HDIM*CDIM];  // W^T lo
__device__ __align__(16) __half g_qh[(size_t)ROWS*HDIM];             // q*scale fp16
__device__ __align__(16) __half g_kh[(size_t)ROWS*HDIM];             // k fp16
__device__ __align__(16) __half g_vh[(size_t)ROWS*HDIM];             // v hi fp16
__device__ __align__(16) __half g_vl[(size_t)ROWS*HDIM];             // v lo fp16

// ---------------------------------------------------------------------------
// Helpers (all vanilla sm_80-era PTX: ldmatrix / mma.sync / cp.async)
// ---------------------------------------------------------------------------
__device__ __forceinline__ uint32_t smem_u32(const void* p) {
    uint32_t a;
    asm("{ .reg .u64 t; cvta.to.shared.u64 t, %1; cvt.u32.u64 %0, t; }"
        : "=r"(a) : "l"(p));
    return a;
}
#define CP_ASYNC16(dst, src) \
    asm volatile("cp.async.cg.shared.global [%0], [%1], 16;" \
                 :: "r"(dst), "l"(src) : "memory")
#define CP_COMMIT() asm volatile("cp.async.commit_group;" ::: "memory")
#define CP_WAIT1()  asm volatile("cp.async.wait_group 1;" ::: "memory")
#define CP_WAIT0()  asm volatile("cp.async.wait_group 0;" ::: "memory")

#define LDSM_X4(r0,r1,r2,r3,addr) \
    asm volatile("ldmatrix.sync.aligned.m8n8.x4.shared.b16 {%0,%1,%2,%3}, [%4];" \
                 : "=r"(r0),"=r"(r1),"=r"(r2),"=r"(r3) : "r"(addr))
#define LDSM_X4T(r0,r1,r2,r3,addr) \
    asm volatile("ldmatrix.sync.aligned.m8n8.x4.trans.shared.b16 {%0,%1,%2,%3}, [%4];" \
                 : "=r"(r0),"=r"(r1),"=r"(r2),"=r"(r3) : "r"(addr))

__device__ __forceinline__ void mma_f16(float c[4], uint32_t a0, uint32_t a1,
                                        uint32_t a2, uint32_t a3,
                                        uint32_t b0, uint32_t b1)
{
    asm volatile(
        "mma.sync.aligned.m16n8k16.row.col.f32.f16.f16.f32 "
        "{%0,%1,%2,%3},{%4,%5,%6,%7},{%8,%9},{%0,%1,%2,%3};"
        : "+f"(c[0]), "+f"(c[1]), "+f"(c[2]), "+f"(c[3])
        : "r"(a0), "r"(a1), "r"(a2), "r"(a3), "r"(b0), "r"(b1));
}
__device__ __forceinline__ void mma_bf16(float c[4], uint32_t a0, uint32_t a1,
                                         uint32_t a2, uint32_t a3,
                                         uint32_t b0, uint32_t b1)
{
    asm volatile(
        "mma.sync.aligned.m16n8k16.row.col.f32.bf16.bf16.f32 "
        "{%0,%1,%2,%3},{%4,%5,%6,%7},{%8,%9},{%0,%1,%2,%3};"
        : "+f"(c[0]), "+f"(c[1]), "+f"(c[2]), "+f"(c[3])
        : "r"(a0), "r"(a1), "r"(a2), "r"(a3), "r"(b0), "r"(b1));
}
// pack {lo, hi} floats -> f16x2 register (first PTX source goes to upper half)
__device__ __forceinline__ uint32_t pack_h2(float lo, float hi) {
    uint32_t d;
    asm("cvt.rn.f16x2.f32 %0, %1, %2;" : "=r"(d) : "f"(hi), "f"(lo));
    return d;
}

// ---------------------------------------------------------------------------
// Prep 1: split X fp32 -> (hi, lo) bf16   (unchanged, proven)
// ---------------------------------------------------------------------------
__global__ __launch_bounds__(256) void split_x_kernel(const float* __restrict__ x)
{
    const size_t n4 = (size_t)ROWS * CDIM / 4;
    __nv_bfloat162* xh2 = reinterpret_cast<__nv_bfloat162*>(g_xhi);
    __nv_bfloat162* xl2 = reinterpret_cast<__nv_bfloat162*>(g_xlo);
    for (size_t i = (size_t)blockIdx.x * blockDim.x + threadIdx.x; i < n4;
         i += (size_t)gridDim.x * blockDim.x) {
        float4 v = reinterpret_cast<const float4*>(x)[i];
        float f[4] = {v.x, v.y, v.z, v.w};
        __nv_bfloat16 h[4], l[4];
        #pragma unroll
        for (int j = 0; j < 4; j++) {
            h[j] = __float2bfloat16_rn(f[j]);
            l[j] = __float2bfloat16_rn(f[j] - __bfloat162float(h[j]));
        }
        __nv_bfloat162 h01; h01.x = h[0]; h01.y = h[1];
        __nv_bfloat162 h23; h23.x = h[2]; h23.y = h[3];
        __nv_bfloat162 l01; l01.x = l[0]; l01.y = l[1];
        __nv_bfloat162 l23; l23.x = l[2]; l23.y = l[3];
        xh2[2*i]   = h01; xh2[2*i+1] = h23;
        xl2[2*i]   = l01; xl2[2*i+1] = l23;
    }
}

// ---------------------------------------------------------------------------
// Prep 2: transpose + split W[2048][128] -> W^T hi/lo [m][128][2048] bf16
// ---------------------------------------------------------------------------
__global__ __launch_bounds__(256) void prep_w_kernel(
    const float* __restrict__ wq, const float* __restrict__ wk, const float* __restrict__ wv)
{
    __shared__ float t[32][33];
    const float* W = (blockIdx.z == 0) ? wq : ((blockIdx.z == 1) ? wk : wv);
    const int k0 = blockIdx.x * 32;
    const int n0 = blockIdx.y * 32;
    const int tx = threadIdx.x, ty = threadIdx.y;   // 32 x 8

    #pragma unroll
    for (int r = 0; r < 32; r += 8)
        t[ty + r][tx] = W[(size_t)(k0 + ty + r) * HDIM + (n0 + tx)];
    __syncthreads();

    size_t base = (size_t)blockIdx.z * HDIM * CDIM;
    #pragma unroll
    for (int r = 0; r < 32; r += 8) {
        int nl = ty + r;
        float v = t[tx][nl];
        __nv_bfloat16 h = __float2bfloat16_rn(v);
        __nv_bfloat16 l = __float2bfloat16_rn(v - __bfloat162float(h));
        size_t o = base + (size_t)(n0 + nl) * CDIM + (k0 + tx);
        g_wthi[o] = h;
        g_wtlo[o] = l;
    }
}

// ---------------------------------------------------------------------------
// QKV GEMM via mma.sync bf16x3.  Block: 128 rows x 128 cols, BK=32.
// 256 thr = 8 warps (4 m x 2 n); warp tile 32x64. cp.async double-buffered.
// Smem tiles padded to 40 halves/row (80B, ldmatrix-aligned, conflict-free).
// ---------------------------------------------------------------------------
#define G_ROWH   40                     // padded halves per row
#define G_ARR    (128*G_ROWH*2)         // 10240 B per array
#define G_STAGE  (4*G_ARR)              // 40960 B per stage
#define G_SMEM   (2*G_STAGE)            // 81920 B

__device__ __forceinline__ void gemm_issue_tile(
    uint32_t smb, int stage, int ki, int m0, size_t wbase, int tid)
{
    const int k0 = ki * 32;
    const uint32_t sb = smb + stage * G_STAGE;
    #pragma unroll
    for (int rep = 0; rep < 8; rep++) {
        int i   = tid + rep * 256;          // 0..2047
        int arr = i >> 9;
        int rem = i & 511;
        int row = rem >> 2, c = rem & 3;
        uint32_t dst = sb + arr * G_ARR + (row * G_ROWH + c * 8) * 2;
        const __nv_bfloat16* src;
        if      (arr == 0) src = g_xhi  + (size_t)(m0 + row) * CDIM + k0 + c * 8;
        else if (arr == 1) src = g_xlo  + (size_t)(m0 + row) * CDIM + k0 + c * 8;
        else if (arr == 2) src = g_wthi + wbase + (size_t)row * CDIM + k0 + c * 8;
        else               src = g_wtlo + wbase + (size_t)row * CDIM + k0 + c * 8;
        CP_ASYNC16(dst, src);
    }
    CP_COMMIT();
}

__global__ __launch_bounds__(256) void qkv_gemm_kernel(
    const float* __restrict__ bq, const float* __restrict__ bk, const float* __restrict__ bv)
{
    extern __shared__ char dsm[];
    const uint32_t smb = smem_u32(dsm);

    const int tid  = threadIdx.x;
    const int lane = tid & 31;
    const int wid  = tid >> 5;
    const int wm   = wid & 3;              // 0..3
    const int wn   = wid >> 2;             // 0..1
    const int m    = blockIdx.y;           // matrix 0=q 1=k 2=v
    const int m0   = blockIdx.x * 128;
    const size_t wbase = (size_t)m * HDIM * CDIM;

    // ldmatrix per-lane address components
    const int rbase = (lane & 7) + ((lane >> 3) & 1) * 8;   // row within 16
    const int khalf = ((lane >> 4) & 1) * 8;                // k sub-chunk

    float C[2][8][4];
    #pragma unroll
    for (int a = 0; a < 2; a++)
        #pragma unroll
        for (int b = 0; b < 8; b++)
            #pragma unroll
            for (int e = 0; e < 4; e++) C[a][b][e] = 0.f;

    gemm_issue_tile(smb, 0, 0, m0, wbase, tid);

    const int NIT = CDIM / 32;              // 64
    for (int ki = 0; ki < NIT; ki++) {
        if (ki + 1 < NIT) { gemm_issue_tile(smb, (ki + 1) & 1, ki + 1, m0, wbase, tid); CP_WAIT1(); }
        else              { CP_WAIT0(); }
        __syncthreads();

        const uint32_t sb  = smb + (ki & 1) * G_STAGE;
        const uint32_t aH  = sb;
        const uint32_t aL  = sb + G_ARR;
        const uint32_t bH  = sb + 2 * G_ARR;
        const uint32_t bL  = sb + 3 * G_ARR;

        #pragma unroll
        for (int ks = 0; ks < 2; ks++) {
            const int k0h = ks * 16 + khalf;
            uint32_t ah[2][4], al[2][4];
            #pragma unroll
            for (int mt = 0; mt < 2; mt++) {
                int row = wm * 32 + mt * 16 + rbase;
                uint32_t ad = aH + (row * G_ROWH + k0h) * 2;
                LDSM_X4(ah[mt][0], ah[mt][1], ah[mt][2], ah[mt][3], ad);
                ad = aL + (row * G_ROWH + k0h) * 2;
                LDSM_X4(al[mt][0], al[mt][1], al[mt][2], al[mt][3], ad);
            }
            #pragma unroll
            for (int np = 0; np < 4; np++) {
                int nrow = wn * 64 + np * 16 + rbase;
                uint32_t bh0, bh1, bh2, bh3, bl0, bl1, bl2, bl3;
                uint32_t bd = bH + (nrow * G_ROWH + k0h) * 2;
                LDSM_X4(bh0, bh1, bh2, bh3, bd);
                bd = bL + (nrow * G_ROWH + k0h) * 2;
                LDSM_X4(bl0, bl1, bl2, bl3, bd);
                #pragma unroll
                for (int mt = 0; mt < 2; mt++) {
                    // n-tile 2np: pair (r0, r2); n-tile 2np+1: pair (r1, r3)
                    mma_bf16(C[mt][2*np],   ah[mt][0],ah[mt][1],ah[mt][2],ah[mt][3], bh0, bh2);
                    mma_bf16(C[mt][2*np],   al[mt][0],al[mt][1],al[mt][2],al[mt][3], bh0, bh2);
                    mma_bf16(C[mt][2*np],   ah[mt][0],ah[mt][1],ah[mt][2],ah[mt][3], bl0, bl2);
                    mma_bf16(C[mt][2*np+1], ah[mt][0],ah[mt][1],ah[mt][2],ah[mt][3], bh1, bh3);
                    mma_bf16(C[mt][2*np+1], al[mt][0],al[mt][1],al[mt][2],al[mt][3], bh1, bh3);
                    mma_bf16(C[mt][2*np+1], ah[mt][0],ah[mt][1],ah[mt][2],ah[mt][3], bl1, bl3);
                }
            }
        }
        __syncthreads();
    }

    // Epilogue: bias add, convert, store fp16 (q scaled; v split hi/lo)
    const float* bias = (m == 0) ? bq : ((m == 1) ? bk : bv);
    const float scale = 0.022097086912079608f;   // 1/sqrt(2048)
    const int g = lane >> 2, t = lane & 3;

    #pragma unroll
    for (int mt = 0; mt < 2; mt++) {
        #pragma unroll
        for (int j = 0; j < 8; j++) {
            int col = wn * 64 + 8 * j + 2 * t;
            float2 b2 = *reinterpret_cast<const float2*>(bias + col);
            #pragma unroll
            for (int half = 0; half < 2; half++) {
                int row = m0 + wm * 32 + mt * 16 + g + half * 8;
                float v0 = C[mt][j][2*half]   + b2.x;
                float v1 = C[mt][j][2*half+1] + b2.y;
                size_t idx2 = ((size_t)row * HDIM + col) >> 1;
                if (m == 0) {
                    __half2 h; h.x = __float2half_rn(v0 * scale); h.y = __float2half_rn(v1 * scale);
                    reinterpret_cast<__half2*>(g_qh)[idx2] = h;
                } else if (m == 1) {
                    __half2 h; h.x = __float2half_rn(v0); h.y = __float2half_rn(v1);
                    reinterpret_cast<__half2*>(g_kh)[idx2] = h;
                } else {
                    __half h0 = __float2half_rn(v0), h1 = __float2half_rn(v1);
                    __half2 hh; hh.x = h0; hh.y = h1;
                    __half2 ll; ll.x = __float2half_rn(v0 - __half2float(h0));
                    ll.y = __float2half_rn(v1 - __half2float(h1));
                    reinterpret_cast<__half2*>(g_vh)[idx2] = hh;
                    reinterpret_cast<__half2*>(g_vl)[idx2] = ll;
                }
            }
        }
    }
}

// ---------------------------------------------------------------------------
// Flash attention via mma.sync fp16.
// Block: 128 thr = 4 warps, 64 queries (16/warp). Key tiles of 64, double-
// buffered cp.async. Q in register A-frags. PV in 3 passes (Phi*Vhi +
// Plo*Vhi + Phi*Vlo) for precision. Smem rows 256B, 16B-chunk XOR swizzle.
// ---------------------------------------------------------------------------
#define A_TILE  16384                       // one 64x128 fp16 tile
#define A_BUF   (3*A_TILE)                  // K | Vhi | Vlo
#define A_SMEM  (2*A_BUF)                   // 98304 B

__device__ __forceinline__ void attn_issue_tile(uint32_t smb, int stage,
                                                int rowbase, int kt, int tid)
{
    const uint32_t sb = smb + stage * A_BUF;
    #pragma unroll
    for (int rep = 0; rep < 24; rep++) {
        int i   = tid + rep * 128;          // 0..3071
        int arr = i >> 10;
        int rem = i & 1023;
        int r = rem >> 4, c = rem & 15;
        uint32_t dst = sb + arr * A_TILE + r * 256 + ((c ^ (r & 7)) * 16);
        const __half* src;
        if      (arr == 0) src = g_kh + (size_t)(rowbase + kt * 64 + r) * HDIM + c * 8;
        else if (arr == 1) src = g_vh + (size_t)(rowbase + kt * 64 + r) * HDIM + c * 8;
        else               src = g_vl + (size_t)(rowbase + kt * 64 + r) * HDIM + c * 8;
        CP_ASYNC16(dst, src);
    }
    CP_COMMIT();
}

__global__ __launch_bounds__(128) void attn_kernel(float* __restrict__ out)
{
    extern __shared__ char dsm[];
    const uint32_t smb = smem_u32(dsm);

    const int tid  = threadIdx.x;
    const int lane = tid & 31;
    const int w    = tid >> 5;              // warp = q sub-tile
    const int bx   = blockIdx.x;            // q block (64 queries)
    const int b    = blockIdx.y;            // batch
    const int q0   = bx * 64;
    const int rowbase = b * SEQ;
    const int ntiles  = bx + 1;

    const int g = lane >> 2, t = lane & 3;
    const int rbase = (lane & 7) + ((lane >> 3) & 1) * 8;
    const int chalf = (lane >> 4) & 1;

    // Kick off tile 0 loads immediately (overlaps Q staging)
    attn_issue_tile(smb, 0, rowbase, 0, tid);

    // Stage Q (64x128 fp16) into buf1's K region, then extract A-frags
    {
        const uint32_t qb = smb + A_BUF;    // buf1 K area
        #pragma unroll
        for (int rep = 0; rep < 8; rep++) {
            int i = tid + rep * 128;        // 0..1023
            int r = i >> 4, c = i & 15;
            uint4 v = *reinterpret_cast<const uint4*>(
                g_qh + (size_t)(rowbase + q0 + r) * HDIM + c * 8);
            *reinterpret_cast<uint4*>(dsm + (A_BUF) + r * 256 + ((c ^ (r & 7)) * 16)) = v;
        }
        (void)qb;
    }
    __syncthreads();

    uint32_t qf[8][4];
    {
        const uint32_t qb = smb + A_BUF;
        int row = w * 16 + rbase;
        #pragma unroll
        for (int kc = 0; kc < 8; kc++) {
            int ch = 2 * kc + chalf;
            uint32_t ad = qb + row * 256 + ((ch ^ (row & 7)) * 16);
            LDSM_X4(qf[kc][0], qf[kc][1], qf[kc][2], qf[kc][3], ad);
        }
    }
    __syncthreads();

    float o[16][4];
    #pragma unroll
    for (int n = 0; n < 16; n++)
        #pragma unroll
        for (int e = 0; e < 4; e++) o[n][e] = 0.f;
    float m0 = -INFINITY, m1 = -INFINITY, l0 = 0.f, l1 = 0.f;

    for (int kt = 0; kt < ntiles; kt++) {
        if (kt + 1 < ntiles) { attn_issue_tile(smb, (kt + 1) & 1, rowbase, kt + 1, tid); CP_WAIT1(); }
        else                 { CP_WAIT0(); }
        __syncthreads();

        const uint32_t kb  = smb + (kt & 1) * A_BUF;
        const uint32_t vhb = kb + A_TILE;
        const uint32_t vlb = kb + 2 * A_TILE;

        // ---- S = Q K^T ----
        float s[8][4];
        #pragma unroll
        for (int j = 0; j < 8; j++)
            #pragma unroll
            for (int e = 0; e < 4; e++) s[j][e] = 0.f;

        #pragma unroll
        for (int jp = 0; jp < 4; jp++) {
            int krow = jp * 16 + rbase;
            #pragma unroll
            for (int kc = 0; kc < 8; kc++) {
                int ch = 2 * kc + chalf;
                uint32_t ad = kb + krow * 256 + ((ch ^ (krow & 7)) * 16);
                uint32_t b0, b1, b2, b3;
                LDSM_X4(b0, b1, b2, b3, ad);
                mma_f16(s[2*jp],   qf[kc][0], qf[kc][1], qf[kc][2], qf[kc][3], b0, b2);
                mma_f16(s[2*jp+1], qf[kc][0], qf[kc][1], qf[kc][2], qf[kc][3], b1, b3);
            }
        }

        // ---- causal mask (only on the diagonal tile) ----
        if (kt == ntiles - 1) {
            #pragma unroll
            for (int j = 0; j < 8; j++) {
                int key = 8 * j + 2 * t;
                int qr0 = 16 * w + g, qr1 = qr0 + 8;
                if (key     > qr0) s[j][0] = -INFINITY;
                if (key + 1 > qr0) s[j][1] = -INFINITY;
                if (key     > qr1) s[j][2] = -INFINITY;
                if (key + 1 > qr1) s[j][3] = -INFINITY;
            }
        }

        // ---- online softmax ----
        float r0 = -INFINITY, r1 = -INFINITY;
        #pragma unroll
        for (int j = 0; j < 8; j++) {
            r0 = fmaxf(r0, fmaxf(s[j][0], s[j][1]));
            r1 = fmaxf(r1, fmaxf(s[j][2], s[j][3]));
        }
        r0 = fmaxf(r0, __shfl_xor_sync(0xffffffffu, r0, 1));
        r0 = fmaxf(r0, __shfl_xor_sync(0xffffffffu, r0, 2));
        r1 = fmaxf(r1, __shfl_xor_sync(0xffffffffu, r1, 1));
        r1 = fmaxf(r1, __shfl_xor_sync(0xffffffffu, r1, 2));

        float mn0 = fmaxf(m0, r0), mn1 = fmaxf(m1, r1);
        float cr0 = __expf(m0 - mn0), cr1 = __expf(m1 - mn1);

        float rs0 = 0.f, rs1 = 0.f;
        #pragma unroll
        for (int j = 0; j < 8; j++) {
            s[j][0] = __expf(s[j][0] - mn0);
            s[j][1] = __expf(s[j][1] - mn0);
            s[j][2] = __expf(s[j][2] - mn1);
            s[j][3] = __expf(s[j][3] - mn1);
            rs0 += s[j][0] + s[j][1];
            rs1 += s[j][2] + s[j][3];
        }
        rs0 += __shfl_xor_sync(0xffffffffu, rs0, 1);
        rs0 += __shfl_xor_sync(0xffffffffu, rs0, 2);
        rs1 += __shfl_xor_sync(0xffffffffu, rs1, 1);
        rs1 += __shfl_xor_sync(0xffffffffu, rs1, 2);

        l0 = l0 * cr0 + rs0;
        l1 = l1 * cr1 + rs1;
        m0 = mn0; m1 = mn1;
        #pragma unroll
        for (int n = 0; n < 16; n++) {
            o[n][0] *= cr0; o[n][1] *= cr0;
            o[n][2] *= cr1; o[n][3] *= cr1;
        }

        // ---- P -> fp16 hi/lo A-frags (pure register work) ----
        uint32_t ahi[4][4], alo[4][4];
        #pragma unroll
        for (int u = 0; u < 4; u++) {
            #pragma unroll
            for (int half = 0; half < 2; half++) {     // half: rows g / g+8
                #pragma unroll
                for (int sub = 0; sub < 2; sub++) {    // sub: k-tile 2u / 2u+1
                    float p0 = s[2*u + sub][2*half];
                    float p1 = s[2*u + sub][2*half + 1];
                    float h0 = __half2float(__float2half_rn(p0));
                    float h1 = __half2float(__float2half_rn(p1));
                    ahi[u][half + 2*sub] = pack_h2(p0, p1);
                    alo[u][half + 2*sub] = pack_h2(p0 - h0, p1 - h1);
                }
            }
        }

        // ---- O += P V  (3 passes) ----
        #pragma unroll
        for (int u = 0; u < 4; u++) {
            int krow = u * 16 + rbase;
            #pragma unroll
            for (int ntp = 0; ntp < 8; ntp++) {
                int ch = 2 * ntp + chalf;
                uint32_t adh = vhb + krow * 256 + ((ch ^ (krow & 7)) * 16);
                uint32_t adl = vlb + krow * 256 + ((ch ^ (krow & 7)) * 16);
                uint32_t h0, h1, h2, h3, e0, e1, e2, e3;
                LDSM_X4T(h0, h1, h2, h3, adh);
                LDSM_X4T(e0, e1, e2, e3, adl);
                mma_f16(o[2*ntp],   ahi[u][0],ahi[u][1],ahi[u][2],ahi[u][3], h0, h1);
                mma_f16(o[2*ntp],   alo[u][0],alo[u][1],alo[u][2],alo[u][3], h0, h1);
                mma_f16(o[2*ntp],   ahi[u][0],ahi[u][1],ahi[u][2],ahi[u][3], e0, e1);
                mma_f16(o[2*ntp+1], ahi[u][0],ahi[u][1],ahi[u][2],ahi[u][3], h2, h3);
                mma_f16(o[2*ntp+1], alo[u][0],alo[u][1],alo[u][2],alo[u][3], h2, h3);
                mma_f16(o[2*ntp+1], ahi[u][0],ahi[u][1],ahi[u][2],ahi[u][3], e2, e3);
            }
        }
        __syncthreads();
    }

    // ---- write O / l ----
    float inv0 = 1.f / l0, inv1 = 1.f / l1;
    int row0 = rowbase + q0 + 16 * w + g;
    #pragma unroll
    for (int j = 0; j < 16; j++) {
        int col = 8 * j + 2 * t;
        float2 v0; v0.x = o[j][0] * inv0; v0.y = o[j][1] * inv0;
        float2 v1; v1.x = o[j][2] * inv1; v1.y = o[j][3] * inv1;
        *reinterpret_cast<float2*>(out + (size_t)row0 * HDIM + col)       = v0;
        *reinterpret_cast<float2*>(out + (size_t)(row0 + 8) * HDIM + col) = v1;
    }
}

// ---------------------------------------------------------------------------
extern "C" void kernel_launch(void* const* d_in, const int* in_sizes, int n_in,
                              void* d_out, int out_size)
{
    const float* x  = (const float*)d_in[0];
    const float* wq = (const float*)d_in[1];
    const float* bq = (const float*)d_in[2];
    const float* wk = (const float*)d_in[3];
    const float* bk = (const float*)d_in[4];
    const float* wv = (const float*)d_in[5];
    const float* bv = (const float*)d_in[6];
    float* out = (float*)d_out;

    cudaFuncSetAttribute(qkv_gemm_kernel,
                         cudaFuncAttributeMaxDynamicSharedMemorySize, G_SMEM);
    cudaFuncSetAttribute(attn_kernel,
                         cudaFuncAttributeMaxDynamicSharedMemorySize, A_SMEM);

    split_x_kernel<<<4096, 256>>>(x);
    prep_w_kernel<<<dim3(CDIM/32, HDIM/32, 3), dim3(32, 8)>>>(wq, wk, wv);
    qkv_gemm_kernel<<<dim3(ROWS/128, 3), 256, G_SMEM>>>(bq, bk, bv);
    attn_kernel<<<dim3(SEQ/64, BATCH), 128, A_SMEM>>>(out);
}

// round 4
// speedup vs baseline: 10.5821x; 1.9560x over previous
#include <cuda_runtime.h>
#include <cuda_fp16.h>
#include <cstdint>
#include <math.h>

#define BATCH 4
#define SEQ   2048
#define CDIM  2048
#define HDIM  128
#define ROWS  (BATCH*SEQ)

// ---------------------------------------------------------------------------
// Device scratch (allocation-free)
// ---------------------------------------------------------------------------
__device__ __align__(16) __half g_xh[(size_t)ROWS*CDIM];     // x fp16, 32 MB
__device__ __align__(16) __half g_wt[(size_t)3*HDIM*CDIM];   // W^T fp16 [384][2048]
__device__ __align__(16) __half g_qh[(size_t)ROWS*HDIM];     // q*scale fp16
__device__ __align__(16) __half g_kh[(size_t)ROWS*HDIM];     // k fp16
__device__ __align__(16) __half g_vh[(size_t)ROWS*HDIM];     // v fp16
__device__ float  g_po[2][(size_t)ROWS*HDIM];                // partial O (unnorm)
__device__ float2 g_pml[2][ROWS];                            // partial (m, l)

// ---------------------------------------------------------------------------
// Helpers (vanilla sm_80-era PTX: ldmatrix / mma.sync / cp.async)
// ---------------------------------------------------------------------------
__device__ __forceinline__ uint32_t smem_u32(const void* p) {
    uint32_t a;
    asm("{ .reg .u64 t; cvta.to.shared.u64 t, %1; cvt.u32.u64 %0, t; }"
        : "=r"(a) : "l"(p));
    return a;
}
#define CP_ASYNC16(dst, src) \
    asm volatile("cp.async.cg.shared.global [%0], [%1], 16;" \
                 :: "r"(dst), "l"(src) : "memory")
#define CP_COMMIT() asm volatile("cp.async.commit_group;" ::: "memory")
#define CP_WAIT1()  asm volatile("cp.async.wait_group 1;" ::: "memory")
#define CP_WAIT0()  asm volatile("cp.async.wait_group 0;" ::: "memory")

#define LDSM_X4(r0,r1,r2,r3,addr) \
    asm volatile("ldmatrix.sync.aligned.m8n8.x4.shared.b16 {%0,%1,%2,%3}, [%4];" \
                 : "=r"(r0),"=r"(r1),"=r"(r2),"=r"(r3) : "r"(addr))
#define LDSM_X4T(r0,r1,r2,r3,addr) \
    asm volatile("ldmatrix.sync.aligned.m8n8.x4.trans.shared.b16 {%0,%1,%2,%3}, [%4];" \
                 : "=r"(r0),"=r"(r1),"=r"(r2),"=r"(r3) : "r"(addr))

__device__ __forceinline__ void mma_f16(float c[4], uint32_t a0, uint32_t a1,
                                        uint32_t a2, uint32_t a3,
                                        uint32_t b0, uint32_t b1)
{
    asm volatile(
        "mma.sync.aligned.m16n8k16.row.col.f32.f16.f16.f32 "
        "{%0,%1,%2,%3},{%4,%5,%6,%7},{%8,%9},{%0,%1,%2,%3};"
        : "+f"(c[0]), "+f"(c[1]), "+f"(c[2]), "+f"(c[3])
        : "r"(a0), "r"(a1), "r"(a2), "r"(a3), "r"(b0), "r"(b1));
}
// pack {lo, hi} floats -> f16x2 register
__device__ __forceinline__ uint32_t pack_h2(float lo, float hi) {
    uint32_t d;
    asm("cvt.rn.f16x2.f32 %0, %1, %2;" : "=r"(d) : "f"(hi), "f"(lo));
    return d;
}

// ---------------------------------------------------------------------------
// Prep 1: convert X fp32 -> fp16
// ---------------------------------------------------------------------------
__global__ __launch_bounds__(256) void cvt_x_kernel(const float* __restrict__ x)
{
    const size_t n8 = (size_t)ROWS * CDIM / 8;
    const float4* x4 = reinterpret_cast<const float4*>(x);
    uint4* xh4 = reinterpret_cast<uint4*>(g_xh);
    for (size_t i = (size_t)blockIdx.x * blockDim.x + threadIdx.x; i < n8;
         i += (size_t)gridDim.x * blockDim.x) {
        float4 a = x4[2*i], b = x4[2*i+1];
        uint4 r;
        r.x = pack_h2(a.x, a.y);
        r.y = pack_h2(a.z, a.w);
        r.z = pack_h2(b.x, b.y);
        r.w = pack_h2(b.z, b.w);
        xh4[i] = r;
    }
}

// ---------------------------------------------------------------------------
// Prep 2: transpose W[2048][128] -> W^T fp16 rows [z*128 + n][k]
// ---------------------------------------------------------------------------
__global__ __launch_bounds__(256) void prep_w_kernel(
    const float* __restrict__ wq, const float* __restrict__ wk, const float* __restrict__ wv)
{
    __shared__ float t[32][33];
    const float* W = (blockIdx.z == 0) ? wq : ((blockIdx.z == 1) ? wk : wv);
    const int k0 = blockIdx.x * 32;
    const int n0 = blockIdx.y * 32;
    const int tx = threadIdx.x, ty = threadIdx.y;   // 32 x 8

    #pragma unroll
    for (int r = 0; r < 32; r += 8)
        t[ty + r][tx] = W[(size_t)(k0 + ty + r) * HDIM + (n0 + tx)];
    __syncthreads();

    #pragma unroll
    for (int r = 0; r < 32; r += 8) {
        int nl = ty + r;
        size_t o = (size_t)(blockIdx.z * HDIM + n0 + nl) * CDIM + (k0 + tx);
        g_wt[o] = __float2half_rn(t[tx][nl]);
    }
}

// ---------------------------------------------------------------------------
// Fused QKV GEMM, single-pass fp16.  Block: 64 rows x 384 cols, BK=32.
// 256 thr = 8 warps (2 m x 4 n); warp tile 32x96. cp.async double-buffered.
// Smem rows padded to 40 halves (80 B) -> conflict-free ldmatrix.
// ---------------------------------------------------------------------------
#define GQ_ROWH    40
#define GQ_A_BYTES (64*GQ_ROWH*2)              // 5120
#define GQ_B_BYTES (384*GQ_ROWH*2)             // 30720
#define GQ_STAGE   (GQ_A_BYTES + GQ_B_BYTES)   // 35840
#define GQ_SMEM    (2*GQ_STAGE)                // 71680

__device__ __forceinline__ void gemm_issue(uint32_t smb, int stage, int ki,
                                           int m0, int tid)
{
    const int k0 = ki * 32;
    const uint32_t sb = smb + stage * GQ_STAGE;
    #pragma unroll
    for (int rep = 0; rep < 7; rep++) {
        int i = tid + rep * 256;               // 0..1791
        if (i < 256) {
            int row = i >> 2, c = i & 3;
            uint32_t dst = sb + (row * GQ_ROWH + c * 8) * 2;
            CP_ASYNC16(dst, g_xh + (size_t)(m0 + row) * CDIM + k0 + c * 8);
        } else {
            int j = i - 256;                   // 0..1535
            int row = j >> 2, c = j & 3;       // row 0..383
            uint32_t dst = sb + GQ_A_BYTES + (row * GQ_ROWH + c * 8) * 2;
            CP_ASYNC16(dst, g_wt + (size_t)row * CDIM + k0 + c * 8);
        }
    }
    CP_COMMIT();
}

__global__ __launch_bounds__(256) void qkv_gemm_kernel(
    const float* __restrict__ bq, const float* __restrict__ bk, const float* __restrict__ bv)
{
    extern __shared__ char dsm[];
    const uint32_t smb = smem_u32(dsm);

    const int tid  = threadIdx.x;
    const int lane = tid & 31;
    const int wid  = tid >> 5;
    const int wm   = wid & 1;                   // 0..1
    const int wn   = wid >> 1;                  // 0..3
    const int m0   = blockIdx.x * 64;

    const int rbase = (lane & 7) + ((lane >> 3) & 1) * 8;
    const int khalf = ((lane >> 4) & 1) * 8;
    const int g = lane >> 2, t = lane & 3;

    float C[2][12][4];
    #pragma unroll
    for (int a = 0; a < 2; a++)
        #pragma unroll
        for (int b = 0; b < 12; b++)
            #pragma unroll
            for (int e = 0; e < 4; e++) C[a][b][e] = 0.f;

    gemm_issue(smb, 0, 0, m0, tid);

    const int NIT = CDIM / 32;                  // 64
    for (int ki = 0; ki < NIT; ki++) {
        if (ki + 1 < NIT) { gemm_issue(smb, (ki + 1) & 1, ki + 1, m0, tid); CP_WAIT1(); }
        else              { CP_WAIT0(); }
        __syncthreads();

        const uint32_t sA = smb + (ki & 1) * GQ_STAGE;
        const uint32_t sB = sA + GQ_A_BYTES;

        #pragma unroll
        for (int ks = 0; ks < 2; ks++) {
            const int k0h = ks * 16 + khalf;
            uint32_t a[2][4];
            #pragma unroll
            for (int mt = 0; mt < 2; mt++) {
                int row = wm * 32 + mt * 16 + rbase;
                LDSM_X4(a[mt][0], a[mt][1], a[mt][2], a[mt][3],
                        sA + (row * GQ_ROWH + k0h) * 2);
            }
            #pragma unroll
            for (int np = 0; np < 6; np++) {
                int nrow = wn * 96 + np * 16 + rbase;
                uint32_t b0, b1, b2, b3;
                LDSM_X4(b0, b1, b2, b3, sB + (nrow * GQ_ROWH + k0h) * 2);
                #pragma unroll
                for (int mt = 0; mt < 2; mt++) {
                    mma_f16(C[mt][2*np],   a[mt][0],a[mt][1],a[mt][2],a[mt][3], b0, b2);
                    mma_f16(C[mt][2*np+1], a[mt][0],a[mt][1],a[mt][2],a[mt][3], b1, b3);
                }
            }
        }
        __syncthreads();
    }

    // Epilogue: bias, scale (q only), fp16 store into g_qh/g_kh/g_vh
    const float scale = 0.022097086912079608f;  // 1/sqrt(2048)
    #pragma unroll
    for (int mt = 0; mt < 2; mt++) {
        #pragma unroll
        for (int nt = 0; nt < 12; nt++) {
            int col0 = wn * 96 + nt * 8;
            int mat  = col0 >> 7;
            int c0   = (col0 & 127) + 2 * t;
            const float* bias = (mat == 0) ? bq : ((mat == 1) ? bk : bv);
            __half* dst       = (mat == 0) ? g_qh : ((mat == 1) ? g_kh : g_vh);
            float sc = (mat == 0) ? scale : 1.f;
            float2 b2 = *reinterpret_cast<const float2*>(bias + c0);
            #pragma unroll
            for (int half = 0; half < 2; half++) {
                int row = m0 + wm * 32 + mt * 16 + g + 8 * half;
                float v0 = (C[mt][nt][2*half]   + b2.x) * sc;
                float v1 = (C[mt][nt][2*half+1] + b2.y) * sc;
                __half2 h; h.x = __float2half_rn(v0); h.y = __float2half_rn(v1);
                *reinterpret_cast<__half2*>(dst + (size_t)row * HDIM + c0) = h;
            }
        }
    }
}

// ---------------------------------------------------------------------------
// Flash attention, split-K x2, fp16 mma.  128 thr = 4 warps, 64 q/CTA.
// Key tiles of 64; K + V single fp16, P hi/lo split.  Partial (o, m, l) out.
// ---------------------------------------------------------------------------
#define A_TILE  16384                       // one 64x128 fp16 tile
#define A_BUF   (2*A_TILE)                  // K | V
#define A_SMEM  (2*A_BUF)                   // 65536

__device__ __forceinline__ void attn_issue_tile(uint32_t smb, int stage,
                                                int rowbase, int kt, int tid)
{
    const uint32_t sb = smb + stage * A_BUF;
    #pragma unroll
    for (int rep = 0; rep < 16; rep++) {
        int i   = tid + rep * 128;          // 0..2047
        int arr = i >> 10;
        int rem = i & 1023;
        int r = rem >> 4, c = rem & 15;
        uint32_t dst = sb + arr * A_TILE + r * 256 + ((c ^ (r & 7)) * 16);
        const __half* src = (arr == 0 ? g_kh : g_vh)
                          + (size_t)(rowbase + kt * 64 + r) * HDIM + c * 8;
        CP_ASYNC16(dst, src);
    }
    CP_COMMIT();
}

__global__ __launch_bounds__(128) void attn_kernel()
{
    extern __shared__ char dsm[];
    const uint32_t smb = smem_u32(dsm);

    const int tid  = threadIdx.x;
    const int lane = tid & 31;
    const int w    = tid >> 5;
    const int bx   = blockIdx.x;            // q block (64 queries)
    const int h    = blockIdx.y;            // key-split half
    const int b    = blockIdx.z;            // batch
    const int q0   = bx * 64;
    const int rowbase = b * SEQ;

    const int T  = bx + 1;                  // total key tiles for this q block
    const int t0 = T >> 1;
    const int kb = h ? t0 : 0;
    const int ke = h ? T  : t0;

    const int g = lane >> 2, t = lane & 3;
    const int rbase = (lane & 7) + ((lane >> 3) & 1) * 8;
    const int chalf = (lane >> 4) & 1;

    float o[16][4];
    #pragma unroll
    for (int n = 0; n < 16; n++)
        #pragma unroll
        for (int e = 0; e < 4; e++) o[n][e] = 0.f;
    float m0 = -INFINITY, m1 = -INFINITY, l0 = 0.f, l1 = 0.f;

    if (kb < ke) {
        attn_issue_tile(smb, 0, rowbase, kb, tid);

        // Stage Q into buf1 K region (overwritten only after frags extracted)
        #pragma unroll
        for (int rep = 0; rep < 8; rep++) {
            int i = tid + rep * 128;
            int r = i >> 4, c = i & 15;
            uint4 v = *reinterpret_cast<const uint4*>(
                g_qh + (size_t)(rowbase + q0 + r) * HDIM + c * 8);
            *reinterpret_cast<uint4*>(dsm + A_BUF + r * 256 + ((c ^ (r & 7)) * 16)) = v;
        }
        __syncthreads();

        uint32_t qf[8][4];
        {
            const uint32_t qb = smb + A_BUF;
            int row = w * 16 + rbase;
            #pragma unroll
            for (int kc = 0; kc < 8; kc++) {
                int ch = 2 * kc + chalf;
                LDSM_X4(qf[kc][0], qf[kc][1], qf[kc][2], qf[kc][3],
                        qb + row * 256 + ((ch ^ (row & 7)) * 16));
            }
        }
        __syncthreads();

        for (int kt = kb; kt < ke; kt++) {
            const int st = (kt - kb) & 1;
            if (kt + 1 < ke) { attn_issue_tile(smb, st ^ 1, rowbase, kt + 1, tid); CP_WAIT1(); }
            else             { CP_WAIT0(); }
            __syncthreads();

            const uint32_t kbuf = smb + st * A_BUF;
            const uint32_t vbuf = kbuf + A_TILE;

            // ---- S = Q K^T ----
            float s[8][4];
            #pragma unroll
            for (int j = 0; j < 8; j++)
                #pragma unroll
                for (int e = 0; e < 4; e++) s[j][e] = 0.f;

            #pragma unroll
            for (int jp = 0; jp < 4; jp++) {
                int krow = jp * 16 + rbase;
                #pragma unroll
                for (int kc = 0; kc < 8; kc++) {
                    int ch = 2 * kc + chalf;
                    uint32_t b0, b1, b2, b3;
                    LDSM_X4(b0, b1, b2, b3, kbuf + krow * 256 + ((ch ^ (krow & 7)) * 16));
                    mma_f16(s[2*jp],   qf[kc][0], qf[kc][1], qf[kc][2], qf[kc][3], b0, b2);
                    mma_f16(s[2*jp+1], qf[kc][0], qf[kc][1], qf[kc][2], qf[kc][3], b1, b3);
                }
            }

            // ---- causal mask (diagonal tile only) ----
            if (kt == bx) {
                #pragma unroll
                for (int j = 0; j < 8; j++) {
                    int key = 8 * j + 2 * t;
                    int qr0 = 16 * w + g, qr1 = qr0 + 8;
                    if (key     > qr0) s[j][0] = -INFINITY;
                    if (key + 1 > qr0) s[j][1] = -INFINITY;
                    if (key     > qr1) s[j][2] = -INFINITY;
                    if (key + 1 > qr1) s[j][3] = -INFINITY;
                }
            }

            // ---- online softmax ----
            float r0 = -INFINITY, r1 = -INFINITY;
            #pragma unroll
            for (int j = 0; j < 8; j++) {
                r0 = fmaxf(r0, fmaxf(s[j][0], s[j][1]));
                r1 = fmaxf(r1, fmaxf(s[j][2], s[j][3]));
            }
            r0 = fmaxf(r0, __shfl_xor_sync(0xffffffffu, r0, 1));
            r0 = fmaxf(r0, __shfl_xor_sync(0xffffffffu, r0, 2));
            r1 = fmaxf(r1, __shfl_xor_sync(0xffffffffu, r1, 1));
            r1 = fmaxf(r1, __shfl_xor_sync(0xffffffffu, r1, 2));

            float mn0 = fmaxf(m0, r0), mn1 = fmaxf(m1, r1);
            float cr0 = __expf(m0 - mn0), cr1 = __expf(m1 - mn1);

            float rs0 = 0.f, rs1 = 0.f;
            #pragma unroll
            for (int j = 0; j < 8; j++) {
                s[j][0] = __expf(s[j][0] - mn0);
                s[j][1] = __expf(s[j][1] - mn0);
                s[j][2] = __expf(s[j][2] - mn1);
                s[j][3] = __expf(s[j][3] - mn1);
                rs0 += s[j][0] + s[j][1];
                rs1 += s[j][2] + s[j][3];
            }
            rs0 += __shfl_xor_sync(0xffffffffu, rs0, 1);
            rs0 += __shfl_xor_sync(0xffffffffu, rs0, 2);
            rs1 += __shfl_xor_sync(0xffffffffu, rs1, 1);
            rs1 += __shfl_xor_sync(0xffffffffu, rs1, 2);

            l0 = l0 * cr0 + rs0;
            l1 = l1 * cr1 + rs1;
            m0 = mn0; m1 = mn1;
            #pragma unroll
            for (int n = 0; n < 16; n++) {
                o[n][0] *= cr0; o[n][1] *= cr0;
                o[n][2] *= cr1; o[n][3] *= cr1;
            }

            // ---- P -> fp16 hi/lo A-frags ----
            uint32_t ahi[4][4], alo[4][4];
            #pragma unroll
            for (int u = 0; u < 4; u++) {
                #pragma unroll
                for (int half = 0; half < 2; half++) {
                    #pragma unroll
                    for (int sub = 0; sub < 2; sub++) {
                        float p0 = s[2*u + sub][2*half];
                        float p1 = s[2*u + sub][2*half + 1];
                        float h0 = __half2float(__float2half_rn(p0));
                        float h1 = __half2float(__float2half_rn(p1));
                        ahi[u][half + 2*sub] = pack_h2(p0, p1);
                        alo[u][half + 2*sub] = pack_h2(p0 - h0, p1 - h1);
                    }
                }
            }

            // ---- O += P V  (hi + lo passes, V single) ----
            #pragma unroll
            for (int u = 0; u < 4; u++) {
                int krow = u * 16 + rbase;
                #pragma unroll
                for (int ntp = 0; ntp < 8; ntp++) {
                    int ch = 2 * ntp + chalf;
                    uint32_t h0, h1, h2, h3;
                    LDSM_X4T(h0, h1, h2, h3, vbuf + krow * 256 + ((ch ^ (krow & 7)) * 16));
                    mma_f16(o[2*ntp],   ahi[u][0],ahi[u][1],ahi[u][2],ahi[u][3], h0, h1);
                    mma_f16(o[2*ntp],   alo[u][0],alo[u][1],alo[u][2],alo[u][3], h0, h1);
                    mma_f16(o[2*ntp+1], ahi[u][0],ahi[u][1],ahi[u][2],ahi[u][3], h2, h3);
                    mma_f16(o[2*ntp+1], alo[u][0],alo[u][1],alo[u][2],alo[u][3], h2, h3);
                }
            }
            __syncthreads();
        }
    }

    // ---- store partials (unnormalized o, plus m, l) ----
    int row0 = rowbase + q0 + 16 * w + g;
    #pragma unroll
    for (int j = 0; j < 16; j++) {
        int col = 8 * j + 2 * t;
        float2 v0; v0.x = o[j][0]; v0.y = o[j][1];
        float2 v1; v1.x = o[j][2]; v1.y = o[j][3];
        *reinterpret_cast<float2*>(g_po[h] + (size_t)row0 * HDIM + col)       = v0;
        *reinterpret_cast<float2*>(g_po[h] + (size_t)(row0 + 8) * HDIM + col) = v1;
    }
    if (t == 0) {
        float2 a; a.x = m0; a.y = l0;
        float2 c; c.x = m1; c.y = l1;
        g_pml[h][row0]     = a;
        g_pml[h][row0 + 8] = c;
    }
}

// ---------------------------------------------------------------------------
// Combine the two key-split partials -> final output
// ---------------------------------------------------------------------------
__global__ __launch_bounds__(256) void combine_kernel(float* __restrict__ out)
{
    int gid = blockIdx.x * 256 + threadIdx.x;   // < ROWS*32 (float4 units)
    int q = gid >> 5;
    float2 ml0 = g_pml[0][q];
    float2 ml1 = g_pml[1][q];
    float M  = fmaxf(ml0.x, ml1.x);
    float e0 = __expf(ml0.x - M);
    float e1 = __expf(ml1.x - M);
    float inv = 1.f / (ml0.y * e0 + ml1.y * e1);
    float4 o0 = reinterpret_cast<const float4*>(g_po[0])[gid];
    float4 o1 = reinterpret_cast<const float4*>(g_po[1])[gid];
    float4 r;
    r.x = (o0.x * e0 + o1.x * e1) * inv;
    r.y = (o0.y * e0 + o1.y * e1) * inv;
    r.z = (o0.z * e0 + o1.z * e1) * inv;
    r.w = (o0.w * e0 + o1.w * e1) * inv;
    reinterpret_cast<float4*>(out)[gid] = r;
}

// ---------------------------------------------------------------------------
extern "C" void kernel_launch(void* const* d_in, const int* in_sizes, int n_in,
                              void* d_out, int out_size)
{
    const float* x  = (const float*)d_in[0];
    const float* wq = (const float*)d_in[1];
    const float* bq = (const float*)d_in[2];
    const float* wk = (const float*)d_in[3];
    const float* bk = (const float*)d_in[4];
    const float* wv = (const float*)d_in[5];
    const float* bv = (const float*)d_in[6];
    float* out = (float*)d_out;

    cudaFuncSetAttribute(qkv_gemm_kernel,
                         cudaFuncAttributeMaxDynamicSharedMemorySize, GQ_SMEM);
    cudaFuncSetAttribute(attn_kernel,
                         cudaFuncAttributeMaxDynamicSharedMemorySize, A_SMEM);

    cvt_x_kernel<<<4096, 256>>>(x);
    prep_w_kernel<<<dim3(CDIM/32, HDIM/32, 3), dim3(32, 8)>>>(wq, wk, wv);
    qkv_gemm_kernel<<<ROWS/64, 256, GQ_SMEM>>>(bq, bk, bv);
    attn_kernel<<<dim3(SEQ/64, 2, BATCH), 128, A_SMEM>>>();
    combine_kernel<<<ROWS*32/256, 256>>>(out);
}

// round 5
// speedup vs baseline: 13.0210x; 1.2305x over previous
#include <cuda_runtime.h>
#include <cuda_fp16.h>
#include <cstdint>
#include <math.h>

#define BATCH 4
#define SEQ   2048
#define CDIM  2048
#define HDIM  128
#define ROWS  (BATCH*SEQ)
#define NSPLIT 4

// ---------------------------------------------------------------------------
// Device scratch (allocation-free)
// ---------------------------------------------------------------------------
__device__ __align__(16) __half g_wt[(size_t)3*HDIM*CDIM];   // W^T fp16 [384][2048]
__device__ __align__(16) __half g_qh[(size_t)ROWS*HDIM];     // q*scale fp16
__device__ __align__(16) __half g_kh[(size_t)ROWS*HDIM];     // k fp16
__device__ __align__(16) __half g_vh[(size_t)ROWS*HDIM];     // v fp16
__device__ float  g_po[NSPLIT][(size_t)ROWS*HDIM];           // partial O (unnorm)
__device__ float2 g_pml[NSPLIT][ROWS];                       // partial (m, l)

// ---------------------------------------------------------------------------
// Helpers (vanilla sm_80-era PTX: ldmatrix / mma.sync / cp.async)
// ---------------------------------------------------------------------------
__device__ __forceinline__ uint32_t smem_u32(const void* p) {
    uint32_t a;
    asm("{ .reg .u64 t; cvta.to.shared.u64 t, %1; cvt.u32.u64 %0, t; }"
        : "=r"(a) : "l"(p));
    return a;
}
#define CP_ASYNC16(dst, src) \
    asm volatile("cp.async.cg.shared.global [%0], [%1], 16;" \
                 :: "r"(dst), "l"(src) : "memory")
#define CP_COMMIT() asm volatile("cp.async.commit_group;" ::: "memory")
#define CP_WAIT2()  asm volatile("cp.async.wait_group 2;" ::: "memory")
#define CP_WAIT1()  asm volatile("cp.async.wait_group 1;" ::: "memory")
#define CP_WAIT0()  asm volatile("cp.async.wait_group 0;" ::: "memory")

#define LDSM_X4(r0,r1,r2,r3,addr) \
    asm volatile("ldmatrix.sync.aligned.m8n8.x4.shared.b16 {%0,%1,%2,%3}, [%4];" \
                 : "=r"(r0),"=r"(r1),"=r"(r2),"=r"(r3) : "r"(addr))
#define LDSM_X4T(r0,r1,r2,r3,addr) \
    asm volatile("ldmatrix.sync.aligned.m8n8.x4.trans.shared.b16 {%0,%1,%2,%3}, [%4];" \
                 : "=r"(r0),"=r"(r1),"=r"(r2),"=r"(r3) : "r"(addr))

__device__ __forceinline__ void mma_f16(float c[4], uint32_t a0, uint32_t a1,
                                        uint32_t a2, uint32_t a3,
                                        uint32_t b0, uint32_t b1)
{
    asm volatile(
        "mma.sync.aligned.m16n8k16.row.col.f32.f16.f16.f32 "
        "{%0,%1,%2,%3},{%4,%5,%6,%7},{%8,%9},{%0,%1,%2,%3};"
        : "+f"(c[0]), "+f"(c[1]), "+f"(c[2]), "+f"(c[3])
        : "r"(a0), "r"(a1), "r"(a2), "r"(a3), "r"(b0), "r"(b1));
}
// pack {lo, hi} floats -> f16x2 register
__device__ __forceinline__ uint32_t pack_h2(float lo, float hi) {
    uint32_t d;
    asm("cvt.rn.f16x2.f32 %0, %1, %2;" : "=r"(d) : "f"(hi), "f"(lo));
    return d;
}

// ---------------------------------------------------------------------------
// Prep: transpose W[2048][128] -> W^T fp16 rows [z*128 + n][k]
// ---------------------------------------------------------------------------
__global__ __launch_bounds__(256) void prep_w_kernel(
    const float* __restrict__ wq, const float* __restrict__ wk, const float* __restrict__ wv)
{
    __shared__ float t[32][33];
    const float* W = (blockIdx.z == 0) ? wq : ((blockIdx.z == 1) ? wk : wv);
    const int k0 = blockIdx.x * 32;
    const int n0 = blockIdx.y * 32;
    const int tx = threadIdx.x, ty = threadIdx.y;   // 32 x 8

    #pragma unroll
    for (int r = 0; r < 32; r += 8)
        t[ty + r][tx] = W[(size_t)(k0 + ty + r) * HDIM + (n0 + tx)];
    __syncthreads();

    #pragma unroll
    for (int r = 0; r < 32; r += 8) {
        int nl = ty + r;
        size_t o = (size_t)(blockIdx.z * HDIM + n0 + nl) * CDIM + (k0 + tx);
        g_wt[o] = __float2half_rn(t[tx][nl]);
    }
}

// ---------------------------------------------------------------------------
// Fused QKV GEMM, fp16 HMMA, X conversion fused into A-path.
// Block: 64 rows x 384 cols, BK=32.  256 thr = 8 warps (2 m x 4 n).
// A: LDG fp32 -> cvt -> STS fp16 (software pipelined in regs).
// B: cp.async double-buffered.  Rows padded to 40 halves (conflict-lite).
// ---------------------------------------------------------------------------
#define GQ_ROWH    40
#define GQ_A_BYTES (64*GQ_ROWH*2)              // 5120
#define GQ_B_BYTES (384*GQ_ROWH*2)             // 30720
#define GQ_STAGE   (GQ_A_BYTES + GQ_B_BYTES)   // 35840
#define GQ_SMEM    (2*GQ_STAGE)                // 71680

__device__ __forceinline__ void gemm_issueB(uint32_t smb, int stage, int ki, int tid)
{
    const int k0 = ki * 32;
    const uint32_t sb = smb + stage * GQ_STAGE + GQ_A_BYTES;
    #pragma unroll
    for (int rep = 0; rep < 6; rep++) {
        int i = tid + rep * 256;               // 0..1535
        int row = i >> 2, c = i & 3;           // row 0..383
        uint32_t dst = sb + (row * GQ_ROWH + c * 8) * 2;
        CP_ASYNC16(dst, g_wt + (size_t)row * CDIM + k0 + c * 8);
    }
    CP_COMMIT();
}

__global__ __launch_bounds__(256) void qkv_gemm_kernel(
    const float* __restrict__ x,
    const float* __restrict__ bq, const float* __restrict__ bk, const float* __restrict__ bv)
{
    extern __shared__ char dsm[];
    const uint32_t smb = smem_u32(dsm);

    const int tid  = threadIdx.x;
    const int lane = tid & 31;
    const int wid  = tid >> 5;
    const int wm   = wid & 1;                   // 0..1
    const int wn   = wid >> 1;                  // 0..3
    const int m0   = blockIdx.x * 64;

    const int rbase = (lane & 7) + ((lane >> 3) & 1) * 8;
    const int khalf = ((lane >> 4) & 1) * 8;
    const int g = lane >> 2, t = lane & 3;

    // A-load mapping: 64 rows x 32 cols fp32, 8 floats/thread
    const int arow = tid >> 2;                  // 0..63
    const int acol = (tid & 3) * 8;             // 0,8,16,24
    const float* aptr = x + (size_t)(m0 + arow) * CDIM + acol;
    const uint32_t asts = (uint32_t)(arow * GQ_ROWH + acol) * 2;

    float C[2][12][4];
    #pragma unroll
    for (int a = 0; a < 2; a++)
        #pragma unroll
        for (int b = 0; b < 12; b++)
            #pragma unroll
            for (int e = 0; e < 4; e++) C[a][b][e] = 0.f;

    float4 ra0 = *reinterpret_cast<const float4*>(aptr);
    float4 ra1 = *reinterpret_cast<const float4*>(aptr + 4);
    gemm_issueB(smb, 0, 0, tid);

    const int NIT = CDIM / 32;                  // 64
    for (int ki = 0; ki < NIT; ki++) {
        // store A regs (fp16) into this stage
        {
            uint4 u;
            u.x = pack_h2(ra0.x, ra0.y);
            u.y = pack_h2(ra0.z, ra0.w);
            u.z = pack_h2(ra1.x, ra1.y);
            u.w = pack_h2(ra1.z, ra1.w);
            *reinterpret_cast<uint4*>(dsm + (ki & 1) * GQ_STAGE + asts) = u;
        }
        float4 rb0, rb1;
        if (ki + 1 < NIT) {
            const float* ap = aptr + (ki + 1) * 32;
            rb0 = *reinterpret_cast<const float4*>(ap);
            rb1 = *reinterpret_cast<const float4*>(ap + 4);
            gemm_issueB(smb, (ki + 1) & 1, ki + 1, tid);
            CP_WAIT1();
        } else {
            CP_WAIT0();
        }
        __syncthreads();

        const uint32_t sA = smb + (ki & 1) * GQ_STAGE;
        const uint32_t sB = sA + GQ_A_BYTES;

        #pragma unroll
        for (int ks = 0; ks < 2; ks++) {
            const int k0h = ks * 16 + khalf;
            uint32_t a[2][4];
            #pragma unroll
            for (int mt = 0; mt < 2; mt++) {
                int row = wm * 32 + mt * 16 + rbase;
                LDSM_X4(a[mt][0], a[mt][1], a[mt][2], a[mt][3],
                        sA + (row * GQ_ROWH + k0h) * 2);
            }
            #pragma unroll
            for (int np = 0; np < 6; np++) {
                int nrow = wn * 96 + np * 16 + rbase;
                uint32_t b0, b1, b2, b3;
                LDSM_X4(b0, b1, b2, b3, sB + (nrow * GQ_ROWH + k0h) * 2);
                #pragma unroll
                for (int mt = 0; mt < 2; mt++) {
                    mma_f16(C[mt][2*np],   a[mt][0],a[mt][1],a[mt][2],a[mt][3], b0, b2);
                    mma_f16(C[mt][2*np+1], a[mt][0],a[mt][1],a[mt][2],a[mt][3], b1, b3);
                }
            }
        }
        __syncthreads();
        ra0 = rb0; ra1 = rb1;
    }

    // Epilogue: bias, scale (q only), fp16 store
    const float scale = 0.022097086912079608f;  // 1/sqrt(2048)
    #pragma unroll
    for (int mt = 0; mt < 2; mt++) {
        #pragma unroll
        for (int nt = 0; nt < 12; nt++) {
            int col0 = wn * 96 + nt * 8;
            int mat  = col0 >> 7;
            int c0   = (col0 & 127) + 2 * t;
            const float* bias = (mat == 0) ? bq : ((mat == 1) ? bk : bv);
            __half* dst       = (mat == 0) ? g_qh : ((mat == 1) ? g_kh : g_vh);
            float sc = (mat == 0) ? scale : 1.f;
            float2 b2 = *reinterpret_cast<const float2*>(bias + c0);
            #pragma unroll
            for (int half = 0; half < 2; half++) {
                int row = m0 + wm * 32 + mt * 16 + g + 8 * half;
                float v0 = (C[mt][nt][2*half]   + b2.x) * sc;
                float v1 = (C[mt][nt][2*half+1] + b2.y) * sc;
                __half2 h; h.x = __float2half_rn(v0); h.y = __float2half_rn(v1);
                *reinterpret_cast<__half2*>(dst + (size_t)row * HDIM + c0) = h;
            }
        }
    }
}

// ---------------------------------------------------------------------------
// Flash attention, split-K x4, fp16 mma, 3-stage cp.async pipeline.
// 128 thr = 4 warps, 64 q/CTA.  Key tiles of 64.  P hi/lo split.
// ---------------------------------------------------------------------------
#define A_TILE  16384                       // one 64x128 fp16 tile
#define A_BUF   (2*A_TILE)                  // K | V per stage
#define A_SMEM  (3*A_BUF)                   // 98304

__device__ __forceinline__ void attn_issue_tile(uint32_t smb, int stage,
                                                int rowbase, int kt, int tid)
{
    const uint32_t sb = smb + stage * A_BUF;
    #pragma unroll
    for (int rep = 0; rep < 16; rep++) {
        int i   = tid + rep * 128;          // 0..2047
        int arr = i >> 10;
        int rem = i & 1023;
        int r = rem >> 4, c = rem & 15;
        uint32_t dst = sb + arr * A_TILE + r * 256 + ((c ^ (r & 7)) * 16);
        const __half* src = (arr == 0 ? g_kh : g_vh)
                          + (size_t)(rowbase + kt * 64 + r) * HDIM + c * 8;
        CP_ASYNC16(dst, src);
    }
    CP_COMMIT();
}

__global__ __launch_bounds__(128) void attn_kernel()
{
    extern __shared__ char dsm[];
    const uint32_t smb = smem_u32(dsm);

    const int tid  = threadIdx.x;
    const int lane = tid & 31;
    const int w    = tid >> 5;
    const int bx   = blockIdx.x;            // q block (64 queries)
    const int h    = blockIdx.y;            // key-split index (0..3)
    const int b    = blockIdx.z;            // batch
    const int q0   = bx * 64;
    const int rowbase = b * SEQ;

    const int T  = bx + 1;                  // total key tiles for this q block
    const int kb = (h * T) >> 2;
    const int ke = ((h + 1) * T) >> 2;

    const int g = lane >> 2, t = lane & 3;
    const int rbase = (lane & 7) + ((lane >> 3) & 1) * 8;
    const int chalf = (lane >> 4) & 1;

    float o[16][4];
    #pragma unroll
    for (int n = 0; n < 16; n++)
        #pragma unroll
        for (int e = 0; e < 4; e++) o[n][e] = 0.f;
    float m0 = -INFINITY, m1 = -INFINITY, l0 = 0.f, l1 = 0.f;

    if (kb < ke) {
        // Stage Q into stage-0 K region, extract frags, then start pipeline
        #pragma unroll
        for (int rep = 0; rep < 8; rep++) {
            int i = tid + rep * 128;
            int r = i >> 4, c = i & 15;
            uint4 v = *reinterpret_cast<const uint4*>(
                g_qh + (size_t)(rowbase + q0 + r) * HDIM + c * 8);
            *reinterpret_cast<uint4*>(dsm + r * 256 + ((c ^ (r & 7)) * 16)) = v;
        }
        __syncthreads();

        uint32_t qf[8][4];
        {
            int row = w * 16 + rbase;
            #pragma unroll
            for (int kc = 0; kc < 8; kc++) {
                int ch = 2 * kc + chalf;
                LDSM_X4(qf[kc][0], qf[kc][1], qf[kc][2], qf[kc][3],
                        smb + row * 256 + ((ch ^ (row & 7)) * 16));
            }
        }
        __syncthreads();

        attn_issue_tile(smb, 0, rowbase, kb, tid);
        if (kb + 1 < ke) attn_issue_tile(smb, 1, rowbase, kb + 1, tid);

        for (int kt = kb; kt < ke; kt++) {
            const int st = (kt - kb) % 3;
            if (kt + 2 < ke)      { attn_issue_tile(smb, (st + 2) % 3, rowbase, kt + 2, tid); CP_WAIT2(); }
            else if (kt + 1 < ke) { CP_WAIT1(); }
            else                  { CP_WAIT0(); }
            __syncthreads();

            const uint32_t kbuf = smb + st * A_BUF;
            const uint32_t vbuf = kbuf + A_TILE;

            // ---- S = Q K^T ----
            float s[8][4];
            #pragma unroll
            for (int j = 0; j < 8; j++)
                #pragma unroll
                for (int e = 0; e < 4; e++) s[j][e] = 0.f;

            #pragma unroll
            for (int jp = 0; jp < 4; jp++) {
                int krow = jp * 16 + rbase;
                #pragma unroll
                for (int kc = 0; kc < 8; kc++) {
                    int ch = 2 * kc + chalf;
                    uint32_t b0, b1, b2, b3;
                    LDSM_X4(b0, b1, b2, b3, kbuf + krow * 256 + ((ch ^ (krow & 7)) * 16));
                    mma_f16(s[2*jp],   qf[kc][0], qf[kc][1], qf[kc][2], qf[kc][3], b0, b2);
                    mma_f16(s[2*jp+1], qf[kc][0], qf[kc][1], qf[kc][2], qf[kc][3], b1, b3);
                }
            }

            // ---- causal mask (diagonal tile only) ----
            if (kt == bx) {
                #pragma unroll
                for (int j = 0; j < 8; j++) {
                    int key = 8 * j + 2 * t;
                    int qr0 = 16 * w + g, qr1 = qr0 + 8;
                    if (key     > qr0) s[j][0] = -INFINITY;
                    if (key + 1 > qr0) s[j][1] = -INFINITY;
                    if (key     > qr1) s[j][2] = -INFINITY;
                    if (key + 1 > qr1) s[j][3] = -INFINITY;
                }
            }

            // ---- online softmax ----
            float r0 = -INFINITY, r1 = -INFINITY;
            #pragma unroll
            for (int j = 0; j < 8; j++) {
                r0 = fmaxf(r0, fmaxf(s[j][0], s[j][1]));
                r1 = fmaxf(r1, fmaxf(s[j][2], s[j][3]));
            }
            r0 = fmaxf(r0, __shfl_xor_sync(0xffffffffu, r0, 1));
            r0 = fmaxf(r0, __shfl_xor_sync(0xffffffffu, r0, 2));
            r1 = fmaxf(r1, __shfl_xor_sync(0xffffffffu, r1, 1));
            r1 = fmaxf(r1, __shfl_xor_sync(0xffffffffu, r1, 2));

            float mn0 = fmaxf(m0, r0), mn1 = fmaxf(m1, r1);
            float cr0 = __expf(m0 - mn0), cr1 = __expf(m1 - mn1);

            float rs0 = 0.f, rs1 = 0.f;
            #pragma unroll
            for (int j = 0; j < 8; j++) {
                s[j][0] = __expf(s[j][0] - mn0);
                s[j][1] = __expf(s[j][1] - mn0);
                s[j][2] = __expf(s[j][2] - mn1);
                s[j][3] = __expf(s[j][3] - mn1);
                rs0 += s[j][0] + s[j][1];
                rs1 += s[j][2] + s[j][3];
            }
            rs0 += __shfl_xor_sync(0xffffffffu, rs0, 1);
            rs0 += __shfl_xor_sync(0xffffffffu, rs0, 2);
            rs1 += __shfl_xor_sync(0xffffffffu, rs1, 1);
            rs1 += __shfl_xor_sync(0xffffffffu, rs1, 2);

            l0 = l0 * cr0 + rs0;
            l1 = l1 * cr1 + rs1;
            m0 = mn0; m1 = mn1;
            #pragma unroll
            for (int n = 0; n < 16; n++) {
                o[n][0] *= cr0; o[n][1] *= cr0;
                o[n][2] *= cr1; o[n][3] *= cr1;
            }

            // ---- P -> fp16 hi/lo A-frags ----
            uint32_t ahi[4][4], alo[4][4];
            #pragma unroll
            for (int u = 0; u < 4; u++) {
                #pragma unroll
                for (int half = 0; half < 2; half++) {
                    #pragma unroll
                    for (int sub = 0; sub < 2; sub++) {
                        float p0 = s[2*u + sub][2*half];
                        float p1 = s[2*u + sub][2*half + 1];
                        float h0 = __half2float(__float2half_rn(p0));
                        float h1 = __half2float(__float2half_rn(p1));
                        ahi[u][half + 2*sub] = pack_h2(p0, p1);
                        alo[u][half + 2*sub] = pack_h2(p0 - h0, p1 - h1);
                    }
                }
            }

            // ---- O += P V  (hi + lo passes) ----
            #pragma unroll
            for (int u = 0; u < 4; u++) {
                int krow = u * 16 + rbase;
                #pragma unroll
                for (int ntp = 0; ntp < 8; ntp++) {
                    int ch = 2 * ntp + chalf;
                    uint32_t h0, h1, h2, h3;
                    LDSM_X4T(h0, h1, h2, h3, vbuf + krow * 256 + ((ch ^ (krow & 7)) * 16));
                    mma_f16(o[2*ntp],   ahi[u][0],ahi[u][1],ahi[u][2],ahi[u][3], h0, h1);
                    mma_f16(o[2*ntp],   alo[u][0],alo[u][1],alo[u][2],alo[u][3], h0, h1);
                    mma_f16(o[2*ntp+1], ahi[u][0],ahi[u][1],ahi[u][2],ahi[u][3], h2, h3);
                    mma_f16(o[2*ntp+1], alo[u][0],alo[u][1],alo[u][2],alo[u][3], h2, h3);
                }
            }
            __syncthreads();
        }
    }

    // ---- store partials (unnormalized o, plus m, l) ----
    int row0 = rowbase + q0 + 16 * w + g;
    #pragma unroll
    for (int j = 0; j < 16; j++) {
        int col = 8 * j + 2 * t;
        float2 v0; v0.x = o[j][0]; v0.y = o[j][1];
        float2 v1; v1.x = o[j][2]; v1.y = o[j][3];
        *reinterpret_cast<float2*>(g_po[h] + (size_t)row0 * HDIM + col)       = v0;
        *reinterpret_cast<float2*>(g_po[h] + (size_t)(row0 + 8) * HDIM + col) = v1;
    }
    if (t == 0) {
        float2 a; a.x = m0; a.y = l0;
        float2 c; c.x = m1; c.y = l1;
        g_pml[h][row0]     = a;
        g_pml[h][row0 + 8] = c;
    }
}

// ---------------------------------------------------------------------------
// Combine the four key-split partials -> final output
// ---------------------------------------------------------------------------
__global__ __launch_bounds__(256) void combine_kernel(float* __restrict__ out)
{
    int gid = blockIdx.x * 256 + threadIdx.x;   // < ROWS*32 (float4 units)
    int q = gid >> 5;
    float2 ml[NSPLIT];
    float M = -INFINITY;
    #pragma unroll
    for (int i = 0; i < NSPLIT; i++) { ml[i] = g_pml[i][q]; M = fmaxf(M, ml[i].x); }
    float e[NSPLIT], den = 0.f;
    #pragma unroll
    for (int i = 0; i < NSPLIT; i++) { e[i] = __expf(ml[i].x - M); den += ml[i].y * e[i]; }
    float inv = 1.f / den;
    float4 r = make_float4(0.f, 0.f, 0.f, 0.f);
    #pragma unroll
    for (int i = 0; i < NSPLIT; i++) {
        float4 oi = reinterpret_cast<const float4*>(g_po[i])[gid];
        r.x = fmaf(oi.x, e[i], r.x);
        r.y = fmaf(oi.y, e[i], r.y);
        r.z = fmaf(oi.z, e[i], r.z);
        r.w = fmaf(oi.w, e[i], r.w);
    }
    r.x *= inv; r.y *= inv; r.z *= inv; r.w *= inv;
    reinterpret_cast<float4*>(out)[gid] = r;
}

// ---------------------------------------------------------------------------
extern "C" void kernel_launch(void* const* d_in, const int* in_sizes, int n_in,
                              void* d_out, int out_size)
{
    const float* x  = (const float*)d_in[0];
    const float* wq = (const float*)d_in[1];
    const float* bq = (const float*)d_in[2];
    const float* wk = (const float*)d_in[3];
    const float* bk = (const float*)d_in[4];
    const float* wv = (const float*)d_in[5];
    const float* bv = (const float*)d_in[6];
    float* out = (float*)d_out;

    cudaFuncSetAttribute(qkv_gemm_kernel,
                         cudaFuncAttributeMaxDynamicSharedMemorySize, GQ_SMEM);
    cudaFuncSetAttribute(attn_kernel,
                         cudaFuncAttributeMaxDynamicSharedMemorySize, A_SMEM);

    prep_w_kernel<<<dim3(CDIM/32, HDIM/32, 3), dim3(32, 8)>>>(wq, wk, wv);
    qkv_gemm_kernel<<<ROWS/64, 256, GQ_SMEM>>>(x, bq, bk, bv);
    attn_kernel<<<dim3(SEQ/64, NSPLIT, BATCH), 128, A_SMEM>>>();
    combine_kernel<<<ROWS*32/256, 256>>>(out);
}